// round 11
// baseline (speedup 1.0000x reference)
#include <cuda_runtime.h>
#include <cuda_bf16.h>
#include <cstdint>

// EdgeConv: message MLP over edges + mean-aggregate + update MLP + residual.
// R11: edge kernel stripped to the LSU floor. P=x@W1a+b1, Q=x@W1b precomputed
// (bf16). Per edge: LDG P/Q fragments + ea directly into registers (no SMEM,
// no barriers in loop), 8 MMA for ea@W1c, h=relu(acc+P+Q), shfl-assembled
// float4 register scatter. W2 folded into node weights (Wu2 = [Wu_t; W2@Wu_b]).

#define ND      64
#define EDIM    16
#define HID     64
#define TILE_N  64
#define MAXN    100000

#define LDW_H   88    // bf16 weight row stride (176B)
#define LDX_H   72    // pq kernel x-tile row stride (144B)

__device__ float         g_agg[(size_t)MAXN * HID];   // sum of h per dst
__device__ float         g_cnt[MAXN];
__device__ __nv_bfloat16 g_P[(size_t)MAXN * HID];     // x@W1a + b1
__device__ __nv_bfloat16 g_Q[(size_t)MAXN * HID];     // x@W1b
__device__ float         g_Wu2[2 * ND * HID];
__device__ float         g_b2u[HID];

static __device__ __forceinline__ uint32_t s2u(const void* p) {
    return (uint32_t)__cvta_generic_to_shared(p);
}
static __device__ __forceinline__ void ldsm_x4(uint32_t addr, uint32_t& r0,
                                               uint32_t& r1, uint32_t& r2,
                                               uint32_t& r3) {
    asm volatile("ldmatrix.sync.aligned.m8n8.x4.shared.b16 {%0,%1,%2,%3}, [%4];"
                 : "=r"(r0), "=r"(r1), "=r"(r2), "=r"(r3) : "r"(addr));
}
static __device__ __forceinline__ void ldsm_x4t(uint32_t addr, uint32_t& r0,
                                                uint32_t& r1, uint32_t& r2,
                                                uint32_t& r3) {
    asm volatile("ldmatrix.sync.aligned.m8n8.x4.trans.shared.b16 {%0,%1,%2,%3}, [%4];"
                 : "=r"(r0), "=r"(r1), "=r"(r2), "=r"(r3) : "r"(addr));
}
static __device__ __forceinline__ void mma16816(float* c, uint32_t a0, uint32_t a1,
                                                uint32_t a2, uint32_t a3,
                                                uint32_t b0, uint32_t b1) {
    asm volatile(
        "mma.sync.aligned.m16n8k16.row.col.f32.bf16.bf16.f32 "
        "{%0,%1,%2,%3}, {%4,%5,%6,%7}, {%8,%9}, {%0,%1,%2,%3};"
        : "+f"(c[0]), "+f"(c[1]), "+f"(c[2]), "+f"(c[3])
        : "r"(a0), "r"(a1), "r"(a2), "r"(a3), "r"(b0), "r"(b1));
}
static __device__ __forceinline__ uint32_t cvt2(float lo, float hi) {
    __nv_bfloat162 p = __floats2bfloat162_rn(lo, hi);
    return *reinterpret_cast<uint32_t*>(&p);
}
static __device__ __forceinline__ float2 bf2f(uint32_t u) {
    return __bfloat1622float2(*reinterpret_cast<__nv_bfloat162*>(&u));
}

// ---------------------------------------------------------------------------
__global__ void zero_kernel(int N) {
    long long i = (long long)blockIdx.x * blockDim.x + threadIdx.x;
    long long stride = (long long)gridDim.x * blockDim.x;
    float4* a4 = reinterpret_cast<float4*>(g_agg);
    long long n4 = (long long)N * (HID / 4);
    float4 z = make_float4(0.f, 0.f, 0.f, 0.f);
    for (long long j = i; j < n4; j += stride) a4[j] = z;
    for (long long j = i; j < N; j += stride) g_cnt[j] = 0.f;
}

// ---------------------------------------------------------------------------
__global__ void w2u_kernel(const float* __restrict__ W2,
                           const float* __restrict__ Wu,
                           const float* __restrict__ b2) {
    int i = blockIdx.x * blockDim.x + threadIdx.x;
    if (i < ND * HID) {
        g_Wu2[i] = Wu[i];
    } else if (i < 2 * ND * HID) {
        int r = i - ND * HID;
        int j = r >> 6, n = r & 63;
        float s = 0.f;
        for (int m = 0; m < HID; m++)
            s += W2[j * HID + m] * Wu[(ND + m) * HID + n];
        g_Wu2[i] = s;
    } else if (i < 2 * ND * HID + HID) {
        int n = i - 2 * ND * HID;
        float s = 0.f;
        for (int m = 0; m < HID; m++)
            s += b2[m] * Wu[(ND + m) * HID + n];
        g_b2u[n] = s;
    }
}

// ---------------------------------------------------------------------------
// pq_kernel: P = x @ W1[0:64] + b1, Q = x @ W1[64:128]; bf16 outputs.
// ---------------------------------------------------------------------------
__global__ void __launch_bounds__(256)
pq_kernel(const float* __restrict__ x, const float* __restrict__ W1,
          const float* __restrict__ b1, int N, int ntiles) {
    extern __shared__ __align__(16) char smq[];
    __nv_bfloat16* sWa = reinterpret_cast<__nv_bfloat16*>(smq);
    __nv_bfloat16* sWb = sWa + 64 * LDW_H;
    __nv_bfloat16* sX  = sWb + 64 * LDW_H;

    const int tid = threadIdx.x;
    for (int i = tid; i < 64 * 64; i += 256) {
        int k = i >> 6, n = i & 63;
        sWa[k * LDW_H + n] = __float2bfloat16_rn(W1[k * HID + n]);
        sWb[k * LDW_H + n] = __float2bfloat16_rn(W1[(64 + k) * HID + n]);
    }
    __syncthreads();

    const int wid = tid >> 5, lane = tid & 31;
    const int gq = lane >> 2, tq = lane & 3;
    const int el = lane >> 1, part = lane & 1;

    float2 bias1[8];
#pragma unroll
    for (int j = 0; j < 8; j++) {
        bias1[j].x = b1[8 * j + 2 * tq];
        bias1[j].y = b1[8 * j + 2 * tq + 1];
    }

    __nv_bfloat16* myX = sX + wid * 16 * LDX_H;
    const uint32_t xBase = s2u(myX) + (((lane & 15) * LDX_H) + 8 * (lane >> 4)) * 2;
    const uint32_t waBase = s2u(sWa) + (((lane & 15) * LDW_H) + 8 * (lane >> 4)) * 2;
    const uint32_t wbBase = s2u(sWb) + (((lane & 15) * LDW_H) + 8 * (lane >> 4)) * 2;

    for (int t = blockIdx.x * 8 + wid; t < ntiles; t += gridDim.x * 8) {
        const int n0 = t * 16;
        {
            const int n = n0 + el;
            uint4* dst = reinterpret_cast<uint4*>(myX + el * LDX_H + part * 32);
            if (n < N) {
                const float4* xr = reinterpret_cast<const float4*>(
                    x + (size_t)n * ND) + part * 8;
#pragma unroll
                for (int i = 0; i < 4; i++) {
                    float4 a = xr[2 * i], b = xr[2 * i + 1];
                    uint4 u;
                    u.x = cvt2(a.x, a.y); u.y = cvt2(a.z, a.w);
                    u.z = cvt2(b.x, b.y); u.w = cvt2(b.z, b.w);
                    dst[i] = u;
                }
            } else {
                uint4 z = make_uint4(0, 0, 0, 0);
#pragma unroll
                for (int i = 0; i < 4; i++) dst[i] = z;
            }
        }
        __syncwarp();

        float accP[8][4], accQ[8][4];
#pragma unroll
        for (int j = 0; j < 8; j++)
#pragma unroll
            for (int q = 0; q < 4; q++) { accP[j][q] = 0.f; accQ[j][q] = 0.f; }

#pragma unroll
        for (int k = 0; k < 4; k++) {
            uint32_t a0, a1, a2, a3;
            ldsm_x4(xBase + k * 32, a0, a1, a2, a3);
#pragma unroll
            for (int nb = 0; nb < 4; nb++) {
                uint32_t p0, p1, p2, p3;
                ldsm_x4t(waBase + (k * 16 * LDW_H + nb * 16) * 2, p0, p1, p2, p3);
                mma16816(accP[2 * nb],     a0, a1, a2, a3, p0, p1);
                mma16816(accP[2 * nb + 1], a0, a1, a2, a3, p2, p3);
                ldsm_x4t(wbBase + (k * 16 * LDW_H + nb * 16) * 2, p0, p1, p2, p3);
                mma16816(accQ[2 * nb],     a0, a1, a2, a3, p0, p1);
                mma16816(accQ[2 * nb + 1], a0, a1, a2, a3, p2, p3);
            }
        }

        const int r0n = n0 + gq, r1n = n0 + gq + 8;
#pragma unroll
        for (int j = 0; j < 8; j++) {
            const int c = 8 * j + 2 * tq;
            if (r0n < N) {
                *reinterpret_cast<uint32_t*>(g_P + (size_t)r0n * HID + c) =
                    cvt2(accP[j][0] + bias1[j].x, accP[j][1] + bias1[j].y);
                *reinterpret_cast<uint32_t*>(g_Q + (size_t)r0n * HID + c) =
                    cvt2(accQ[j][0], accQ[j][1]);
            }
            if (r1n < N) {
                *reinterpret_cast<uint32_t*>(g_P + (size_t)r1n * HID + c) =
                    cvt2(accP[j][2] + bias1[j].x, accP[j][3] + bias1[j].y);
                *reinterpret_cast<uint32_t*>(g_Q + (size_t)r1n * HID + c) =
                    cvt2(accQ[j][2], accQ[j][3]);
            }
        }
        __syncwarp();
    }
}

// ---------------------------------------------------------------------------
// Edge kernel: 512 thr (16 warps), 1 CTA/SM. Per warp-tile of 16 edges:
// all operands LDG'd straight into registers; no SMEM/barriers in the loop.
// ---------------------------------------------------------------------------
__global__ void __launch_bounds__(512, 1)
edge_kernel(const int* __restrict__ eidx, const float* __restrict__ ea,
            const float* __restrict__ W1, int E, int nt) {
    __shared__ __align__(16) __nv_bfloat16 sW1c[16 * LDW_H];
    const int tid = threadIdx.x;
    for (int i = tid; i < 16 * HID; i += 512) {
        int k = i >> 6, n = i & 63;
        sW1c[k * LDW_H + n] = __float2bfloat16_rn(W1[(128 + k) * HID + n]);
    }
    __syncthreads();

    const int wid = tid >> 5, lane = tid & 31;
    const int gq = lane >> 2, tq = lane & 3;

    // hoisted B fragments for ea @ W1c
    const uint32_t w1cBase = s2u(sW1c) + (((lane & 15) * LDW_H) + 8 * (lane >> 4)) * 2;
    uint32_t w1f[4][4];
#pragma unroll
    for (int nb = 0; nb < 4; nb++)
        ldsm_x4t(w1cBase + (nb * 16) * 2, w1f[nb][0], w1f[nb][1],
                 w1f[nb][2], w1f[nb][3]);

    const int gw = blockIdx.x * 16 + wid;
    const int gs = gridDim.x * 16;
    const int* __restrict__ srcp = eidx;
    const int* __restrict__ dstp = eidx + E;

    // prefetch indices for first tile (rows gq and gq+8)
    int sA = 0, sB = 0, dA = -1, dB = -1;
    if (gw < nt) {
        const int eA = gw * 16 + gq, eB = eA + 8;
        if (eA < E) { sA = srcp[eA]; dA = dstp[eA]; }
        if (eB < E) { sB = srcp[eB]; dB = dstp[eB]; }
    }

    for (int t = gw; t < nt; t += gs) {
        // ---- issue ea loads (f32, fragment positions) ----
        const float2* eaA = reinterpret_cast<const float2*>(
            ea + (size_t)(t * 16 + gq) * EDIM);
        const float2* eaB = reinterpret_cast<const float2*>(
            ea + (size_t)(t * 16 + gq + 8) * EDIM);
        float2 e0 = make_float2(0.f, 0.f), e1 = e0, e2 = e0, e3 = e0;
        if (dA >= 0) { e0 = eaA[tq]; e1 = eaA[tq + 4]; }
        if (dB >= 0) { e2 = eaB[tq]; e3 = eaB[tq + 4]; }

        // ---- issue P/Q fragment loads (bf16x2 at cols 8j+2tq) ----
        const uint32_t* Pa = reinterpret_cast<const uint32_t*>(g_P + (size_t)sA * HID);
        const uint32_t* Qa = reinterpret_cast<const uint32_t*>(g_Q + (size_t)sA * HID);
        const uint32_t* Pb = reinterpret_cast<const uint32_t*>(g_P + (size_t)sB * HID);
        const uint32_t* Qb = reinterpret_cast<const uint32_t*>(g_Q + (size_t)sB * HID);
        // NOTE: P of src, Q of dst
        const uint32_t* QdA = reinterpret_cast<const uint32_t*>(g_Q + (size_t)((dA >= 0) ? dA : 0) * HID);
        const uint32_t* QdB = reinterpret_cast<const uint32_t*>(g_Q + (size_t)((dB >= 0) ? dB : 0) * HID);
        uint32_t pA[8], qA[8], pB[8], qB[8];
#pragma unroll
        for (int j = 0; j < 8; j++) {
            pA[j] = Pa[tq + 4 * j];
            qA[j] = QdA[tq + 4 * j];
            pB[j] = Pb[tq + 4 * j];
            qB[j] = QdB[tq + 4 * j];
        }
        (void)Qa; (void)Qb;

        // ---- prefetch indices for next tile (overlaps compute) ----
        int nsA = 0, nsB = 0, ndA = -1, ndB = -1;
        {
            const int tn = t + gs;
            if (tn < nt) {
                const int eA = tn * 16 + gq, eB = eA + 8;
                if (eA < E) { nsA = srcp[eA]; ndA = dstp[eA]; }
                if (eB < E) { nsB = srcp[eB]; ndB = dstp[eB]; }
            }
        }

        // ---- A fragment from ea ----
        const uint32_t a0 = cvt2(e0.x, e0.y);
        const uint32_t a1 = cvt2(e2.x, e2.y);
        const uint32_t a2 = cvt2(e1.x, e1.y);
        const uint32_t a3 = cvt2(e3.x, e3.y);

        // ---- MMA: ea(16x16) @ W1c(16x64) ----
        float acc[8][4];
#pragma unroll
        for (int j = 0; j < 8; j++)
#pragma unroll
            for (int q = 0; q < 4; q++) acc[j][q] = 0.f;
#pragma unroll
        for (int nb = 0; nb < 4; nb++) {
            mma16816(acc[2 * nb],     a0, a1, a2, a3, w1f[nb][0], w1f[nb][1]);
            mma16816(acc[2 * nb + 1], a0, a1, a2, a3, w1f[nb][2], w1f[nb][3]);
        }

        // ---- h = relu(acc + P[src] + Q[dst]) (b1 folded into P) ----
#pragma unroll
        for (int j = 0; j < 8; j++) {
            float2 pa = bf2f(pA[j]), qa = bf2f(qA[j]);
            float2 pb = bf2f(pB[j]), qb = bf2f(qB[j]);
            acc[j][0] = fmaxf(acc[j][0] + pa.x + qa.x, 0.f);
            acc[j][1] = fmaxf(acc[j][1] + pa.y + qa.y, 0.f);
            acc[j][2] = fmaxf(acc[j][2] + pb.x + qb.x, 0.f);
            acc[j][3] = fmaxf(acc[j][3] + pb.y + qb.y, 0.f);
        }

        // ---- shfl-assemble float4s and scatter ----
        // even tq: row gq (dst dA), cols 8j + ((tq&2)<<1) .. +3
        // odd tq:  row gq+8 (dst dB), same col base
        const int myd = (tq & 1) ? dB : dA;
        float* base = g_agg + (size_t)((myd >= 0) ? myd : 0) * HID + ((tq & 2) << 1);
#pragma unroll
        for (int j = 0; j < 8; j++) {
            float ox = __shfl_xor_sync(0xFFFFFFFFu, acc[j][0], 1);
            float oy = __shfl_xor_sync(0xFFFFFFFFu, acc[j][1], 1);
            float tx = __shfl_xor_sync(0xFFFFFFFFu, acc[j][2], 1);
            float ty = __shfl_xor_sync(0xFFFFFFFFu, acc[j][3], 1);
            if (myd >= 0) {
                float4 v;
                if ((tq & 1) == 0)
                    v = make_float4(acc[j][0], acc[j][1], ox, oy);
                else
                    v = make_float4(tx, ty, acc[j][2], acc[j][3]);
                atomicAdd(reinterpret_cast<float4*>(base + 8 * j), v);
            }
        }
        if (tq == 0 && dA >= 0) atomicAdd(&g_cnt[dA], 1.0f);
        if (tq == 1 && dB >= 0) atomicAdd(&g_cnt[dB], 1.0f);

        sA = nsA; sB = nsB; dA = ndA; dB = ndB;
    }
}

// ---------------------------------------------------------------------------
// Node kernel: out = x + relu([x, mean_h] @ Wu2 + bu + f*b2u), f = cnt*inv.
// ---------------------------------------------------------------------------
#define FMA16(ACC, AV, BV)                                                    \
  ACC[0][0] = fmaf(AV.x, BV.x, ACC[0][0]);                                    \
  ACC[0][1] = fmaf(AV.x, BV.y, ACC[0][1]);                                    \
  ACC[0][2] = fmaf(AV.x, BV.z, ACC[0][2]);                                    \
  ACC[0][3] = fmaf(AV.x, BV.w, ACC[0][3]);                                    \
  ACC[1][0] = fmaf(AV.y, BV.x, ACC[1][0]);                                    \
  ACC[1][1] = fmaf(AV.y, BV.y, ACC[1][1]);                                    \
  ACC[1][2] = fmaf(AV.y, BV.z, ACC[1][2]);                                    \
  ACC[1][3] = fmaf(AV.y, BV.w, ACC[1][3]);                                    \
  ACC[2][0] = fmaf(AV.z, BV.x, ACC[2][0]);                                    \
  ACC[2][1] = fmaf(AV.z, BV.y, ACC[2][1]);                                    \
  ACC[2][2] = fmaf(AV.z, BV.z, ACC[2][2]);                                    \
  ACC[2][3] = fmaf(AV.z, BV.w, ACC[2][3]);                                    \
  ACC[3][0] = fmaf(AV.w, BV.x, ACC[3][0]);                                    \
  ACC[3][1] = fmaf(AV.w, BV.y, ACC[3][1]);                                    \
  ACC[3][2] = fmaf(AV.w, BV.z, ACC[3][2]);                                    \
  ACC[3][3] = fmaf(AV.w, BV.w, ACC[3][3]);

__global__ void __launch_bounds__(256, 3)
node_kernel(const float* __restrict__ x, const float* __restrict__ bu,
            float* __restrict__ out, int N, int ntiles) {
    extern __shared__ float smn[];
    float* sWu  = smn;
    float* sIn  = sWu + 2 * ND * HID;
    float* sBu  = sIn + 2 * ND * TILE_N;
    float* sB2u = sBu + HID;
    float* sF   = sB2u + HID;

    const int tid = threadIdx.x;
    for (int i = tid; i < 2 * ND * HID; i += 256) sWu[i] = g_Wu2[i];
    if (tid < HID) { sBu[tid] = bu[tid]; sB2u[tid] = g_b2u[tid]; }
    __syncthreads();

    const int tx = tid & 15;
    const int ty = tid >> 4;
    const int q  = tid & 3;
    const int ng = tid >> 2;

    for (int tile = blockIdx.x; tile < ntiles; tile += gridDim.x) {
        const int n0 = tile * TILE_N;
        {
            const int n = n0 + ng;
            if (n < N) {
                const float cnt = g_cnt[n];
                const float inv = 1.0f / (cnt + 1e-6f);
                if (q == 0) sF[ng] = cnt * inv;
                const float4* xr = reinterpret_cast<const float4*>(x + (size_t)n * ND);
                const float4* ar = reinterpret_cast<const float4*>(g_agg + (size_t)n * HID);
#pragma unroll
                for (int i = 0; i < 4; i++) {
                    const int f4 = q + 4 * i;
                    const int k  = f4 * 4;
                    float4 v = xr[f4];
                    sIn[(k + 0) * TILE_N + ng] = v.x;
                    sIn[(k + 1) * TILE_N + ng] = v.y;
                    sIn[(k + 2) * TILE_N + ng] = v.z;
                    sIn[(k + 3) * TILE_N + ng] = v.w;
                    float4 w = ar[f4];
                    sIn[(ND + k + 0) * TILE_N + ng] = w.x * inv;
                    sIn[(ND + k + 1) * TILE_N + ng] = w.y * inv;
                    sIn[(ND + k + 2) * TILE_N + ng] = w.z * inv;
                    sIn[(ND + k + 3) * TILE_N + ng] = w.w * inv;
                }
            }
        }
        __syncthreads();

        float acc[4][4];
#pragma unroll
        for (int a = 0; a < 4; a++)
#pragma unroll
            for (int b = 0; b < 4; b++) acc[a][b] = 0.f;

#pragma unroll 8
        for (int k = 0; k < 2 * ND; k++) {
            float4 av = *reinterpret_cast<const float4*>(&sIn[k * TILE_N + tx * 4]);
            float4 bv = *reinterpret_cast<const float4*>(&sWu[k * HID + ty * 4]);
            FMA16(acc, av, bv)
        }

#pragma unroll
        for (int ei = 0; ei < 4; ei++) {
            const int n = n0 + tx * 4 + ei;
            if (n < N) {
                const float f = sF[tx * 4 + ei];
                float4 o;
                float r;
                r = acc[ei][0] + sBu[ty * 4 + 0] + f * sB2u[ty * 4 + 0];
                o.x = sIn[(ty * 4 + 0) * TILE_N + tx * 4 + ei] + (r > 0.f ? r : 0.f);
                r = acc[ei][1] + sBu[ty * 4 + 1] + f * sB2u[ty * 4 + 1];
                o.y = sIn[(ty * 4 + 1) * TILE_N + tx * 4 + ei] + (r > 0.f ? r : 0.f);
                r = acc[ei][2] + sBu[ty * 4 + 2] + f * sB2u[ty * 4 + 2];
                o.z = sIn[(ty * 4 + 2) * TILE_N + tx * 4 + ei] + (r > 0.f ? r : 0.f);
                r = acc[ei][3] + sBu[ty * 4 + 3] + f * sB2u[ty * 4 + 3];
                o.w = sIn[(ty * 4 + 3) * TILE_N + tx * 4 + ei] + (r > 0.f ? r : 0.f);
                *reinterpret_cast<float4*>(out + (size_t)n * HID + ty * 4) = o;
            }
        }
        __syncthreads();
    }
}

// ---------------------------------------------------------------------------
extern "C" void kernel_launch(void* const* d_in, const int* in_sizes, int n_in,
                              void* d_out, int out_size) {
    const float* x   = (const float*)d_in[0];
    const int*   ei  = (const int*)d_in[1];
    const float* ea  = (const float*)d_in[2];
    const float* W1  = (const float*)d_in[3];
    const float* b1  = (const float*)d_in[4];
    const float* W2  = (const float*)d_in[5];
    const float* b2  = (const float*)d_in[6];
    const float* Wu  = (const float*)d_in[7];
    const float* bu  = (const float*)d_in[8];
    float* out = (float*)d_out;

    const int N = in_sizes[0] / ND;     // 100000
    const int E = in_sizes[2] / EDIM;   // 1600000

    const int smem_pq   = (2 * 64 * LDW_H + 8 * 16 * LDX_H) * 2;
    const int smem_node = (2 * ND * HID + 2 * ND * TILE_N + 3 * HID) * 4;

    cudaFuncSetAttribute(pq_kernel, cudaFuncAttributeMaxDynamicSharedMemorySize,
                         smem_pq);
    cudaFuncSetAttribute(node_kernel, cudaFuncAttributeMaxDynamicSharedMemorySize,
                         smem_node);

    const int npq = (N + 15) / 16;
    const int nst = (E + 15) / 16;
    const int ntiles = (N + TILE_N - 1) / TILE_N;

    zero_kernel<<<2048, 256>>>(N);
    w2u_kernel<<<(2 * ND * HID + HID + 255) / 256, 256>>>(W2, Wu, b2);
    pq_kernel<<<(npq + 7) / 8, 256, smem_pq>>>(x, W1, b1, N, npq);
    edge_kernel<<<148, 512>>>(ei, ea, W1, E, nst);
    node_kernel<<<456, 256, smem_node>>>(x, bu, out, N, ntiles);
}

// round 12
// speedup vs baseline: 1.3839x; 1.3839x over previous
#include <cuda_runtime.h>
#include <cuda_bf16.h>
#include <cstdint>

// EdgeConv: message MLP over edges + mean-aggregate + update MLP + residual.
// R12: R10 pipeline + fragment-permuted hidden layout p(8j+2t+b)=16t+2j+b for
// P/Q/agg. Epilogue P/Q reads become LDS.128; scatter goes straight from
// accumulator registers as contiguous RED.128 (no STS/LDS bounce); node kernel
// consumes permuted agg via permuted folded weights. W2 folded into Wu.

#define ND      64
#define EDIM    16
#define HID     64
#define TILE_N  64
#define MAXN    100000

#define LDW_H   88    // bf16 weight row stride (176B)
#define LDX_H   72    // pq x-tile row stride (144B)
#define ROWB    272   // edge-kernel P/Q row stride bytes (68 words; conflict-free)

__device__ float         g_agg[(size_t)MAXN * HID];   // permuted h-sums
__device__ float         g_cnt[MAXN];
__device__ __nv_bfloat16 g_P[(size_t)MAXN * HID];     // permuted x@W1a + b1
__device__ __nv_bfloat16 g_Q[(size_t)MAXN * HID];     // permuted x@W1b
__device__ float         g_Wu2[2 * ND * HID];         // [Wu_top; perm(W2@Wu_bot)]
__device__ float         g_b2u[HID];

static __device__ __forceinline__ uint32_t s2u(const void* p) {
    return (uint32_t)__cvta_generic_to_shared(p);
}
static __device__ __forceinline__ void cp16(uint32_t dst, const void* src) {
    asm volatile("cp.async.cg.shared.global [%0], [%1], 16;" :: "r"(dst), "l"(src));
}
static __device__ __forceinline__ void ldsm_x4(uint32_t addr, uint32_t& r0,
                                               uint32_t& r1, uint32_t& r2,
                                               uint32_t& r3) {
    asm volatile("ldmatrix.sync.aligned.m8n8.x4.shared.b16 {%0,%1,%2,%3}, [%4];"
                 : "=r"(r0), "=r"(r1), "=r"(r2), "=r"(r3) : "r"(addr));
}
static __device__ __forceinline__ void ldsm_x4t(uint32_t addr, uint32_t& r0,
                                                uint32_t& r1, uint32_t& r2,
                                                uint32_t& r3) {
    asm volatile("ldmatrix.sync.aligned.m8n8.x4.trans.shared.b16 {%0,%1,%2,%3}, [%4];"
                 : "=r"(r0), "=r"(r1), "=r"(r2), "=r"(r3) : "r"(addr));
}
static __device__ __forceinline__ void mma16816(float* c, uint32_t a0, uint32_t a1,
                                                uint32_t a2, uint32_t a3,
                                                uint32_t b0, uint32_t b1) {
    asm volatile(
        "mma.sync.aligned.m16n8k16.row.col.f32.bf16.bf16.f32 "
        "{%0,%1,%2,%3}, {%4,%5,%6,%7}, {%8,%9}, {%0,%1,%2,%3};"
        : "+f"(c[0]), "+f"(c[1]), "+f"(c[2]), "+f"(c[3])
        : "r"(a0), "r"(a1), "r"(a2), "r"(a3), "r"(b0), "r"(b1));
}
static __device__ __forceinline__ uint32_t cvt2(float lo, float hi) {
    __nv_bfloat162 p = __floats2bfloat162_rn(lo, hi);
    return *reinterpret_cast<uint32_t*>(&p);
}
static __device__ __forceinline__ float2 bf2f(uint32_t u) {
    return __bfloat1622float2(*reinterpret_cast<__nv_bfloat162*>(&u));
}

// ---------------------------------------------------------------------------
__global__ void zero_kernel(int N) {
    long long i = (long long)blockIdx.x * blockDim.x + threadIdx.x;
    long long stride = (long long)gridDim.x * blockDim.x;
    float4* a4 = reinterpret_cast<float4*>(g_agg);
    long long n4 = (long long)N * (HID / 4);
    float4 z = make_float4(0.f, 0.f, 0.f, 0.f);
    for (long long j = i; j < n4; j += stride) a4[j] = z;
    for (long long j = i; j < N; j += stride) g_cnt[j] = 0.f;
}

// ---------------------------------------------------------------------------
// w2u: top = Wu rows [0,64); bottom row r (permuted position) = (W2@Wu_b)[m]
// with m = inv-perm(r): r = 16t+2j+b -> m = 8j+2t+b. b2u = b2@Wu_b.
// ---------------------------------------------------------------------------
__global__ void w2u_kernel(const float* __restrict__ W2,
                           const float* __restrict__ Wu,
                           const float* __restrict__ b2) {
    int i = blockIdx.x * blockDim.x + threadIdx.x;
    if (i < ND * HID) {
        g_Wu2[i] = Wu[i];
    } else if (i < 2 * ND * HID) {
        int r = (i - ND * HID) >> 6, n = i & 63;
        int tt = r >> 4, jj = (r & 15) >> 1, bb = r & 1;
        int m = 8 * jj + 2 * tt + bb;
        float s = 0.f;
        for (int k = 0; k < HID; k++)
            s += W2[m * HID + k] * Wu[(ND + k) * HID + n];
        g_Wu2[i] = s;
    } else if (i < 2 * ND * HID + HID) {
        int n = i - 2 * ND * HID;
        float s = 0.f;
        for (int k = 0; k < HID; k++)
            s += b2[k] * Wu[(ND + k) * HID + n];
        g_b2u[n] = s;
    }
}

// ---------------------------------------------------------------------------
// pq_kernel: P = x@W1[0:64] + b1, Q = x@W1[64:128]; permuted bf16 outputs.
// Lane (gq,tq) owns fragment cols 8j+2tq -> stored at u32 index 8tq+j
// (32B contiguous per row half) -> uint4 stores.
// ---------------------------------------------------------------------------
__global__ void __launch_bounds__(256)
pq_kernel(const float* __restrict__ x, const float* __restrict__ W1,
          const float* __restrict__ b1, int N, int ntiles) {
    extern __shared__ __align__(16) char smq[];
    __nv_bfloat16* sWa = reinterpret_cast<__nv_bfloat16*>(smq);
    __nv_bfloat16* sWb = sWa + 64 * LDW_H;
    __nv_bfloat16* sX  = sWb + 64 * LDW_H;

    const int tid = threadIdx.x;
    for (int i = tid; i < 64 * 64; i += 256) {
        int k = i >> 6, n = i & 63;
        sWa[k * LDW_H + n] = __float2bfloat16_rn(W1[k * HID + n]);
        sWb[k * LDW_H + n] = __float2bfloat16_rn(W1[(64 + k) * HID + n]);
    }
    __syncthreads();

    const int wid = tid >> 5, lane = tid & 31;
    const int gq = lane >> 2, tq = lane & 3;
    const int el = lane >> 1, part = lane & 1;

    float2 bias1[8];
#pragma unroll
    for (int j = 0; j < 8; j++) {
        bias1[j].x = b1[8 * j + 2 * tq];
        bias1[j].y = b1[8 * j + 2 * tq + 1];
    }

    __nv_bfloat16* myX = sX + wid * 16 * LDX_H;
    const uint32_t xBase = s2u(myX) + (((lane & 15) * LDX_H) + 8 * (lane >> 4)) * 2;
    const uint32_t waBase = s2u(sWa) + (((lane & 15) * LDW_H) + 8 * (lane >> 4)) * 2;
    const uint32_t wbBase = s2u(sWb) + (((lane & 15) * LDW_H) + 8 * (lane >> 4)) * 2;

    for (int t = blockIdx.x * 8 + wid; t < ntiles; t += gridDim.x * 8) {
        const int n0 = t * 16;
        {
            const int n = n0 + el;
            uint4* dst = reinterpret_cast<uint4*>(myX + el * LDX_H + part * 32);
            if (n < N) {
                const float4* xr = reinterpret_cast<const float4*>(
                    x + (size_t)n * ND) + part * 8;
#pragma unroll
                for (int i = 0; i < 4; i++) {
                    float4 a = xr[2 * i], b = xr[2 * i + 1];
                    uint4 u;
                    u.x = cvt2(a.x, a.y); u.y = cvt2(a.z, a.w);
                    u.z = cvt2(b.x, b.y); u.w = cvt2(b.z, b.w);
                    dst[i] = u;
                }
            } else {
                uint4 z = make_uint4(0, 0, 0, 0);
#pragma unroll
                for (int i = 0; i < 4; i++) dst[i] = z;
            }
        }
        __syncwarp();

        float accP[8][4], accQ[8][4];
#pragma unroll
        for (int j = 0; j < 8; j++)
#pragma unroll
            for (int q = 0; q < 4; q++) { accP[j][q] = 0.f; accQ[j][q] = 0.f; }

#pragma unroll
        for (int k = 0; k < 4; k++) {
            uint32_t a0, a1, a2, a3;
            ldsm_x4(xBase + k * 32, a0, a1, a2, a3);
#pragma unroll
            for (int nb = 0; nb < 4; nb++) {
                uint32_t p0, p1, p2, p3;
                ldsm_x4t(waBase + (k * 16 * LDW_H + nb * 16) * 2, p0, p1, p2, p3);
                mma16816(accP[2 * nb],     a0, a1, a2, a3, p0, p1);
                mma16816(accP[2 * nb + 1], a0, a1, a2, a3, p2, p3);
                ldsm_x4t(wbBase + (k * 16 * LDW_H + nb * 16) * 2, p0, p1, p2, p3);
                mma16816(accQ[2 * nb],     a0, a1, a2, a3, p0, p1);
                mma16816(accQ[2 * nb + 1], a0, a1, a2, a3, p2, p3);
            }
        }

        const int r0n = n0 + gq, r1n = n0 + gq + 8;
        uint4 u;
        if (r0n < N) {
            uint32_t* Pp = reinterpret_cast<uint32_t*>(g_P + (size_t)r0n * HID) + 8 * tq;
            uint32_t* Qp = reinterpret_cast<uint32_t*>(g_Q + (size_t)r0n * HID) + 8 * tq;
            u.x = cvt2(accP[0][0] + bias1[0].x, accP[0][1] + bias1[0].y);
            u.y = cvt2(accP[1][0] + bias1[1].x, accP[1][1] + bias1[1].y);
            u.z = cvt2(accP[2][0] + bias1[2].x, accP[2][1] + bias1[2].y);
            u.w = cvt2(accP[3][0] + bias1[3].x, accP[3][1] + bias1[3].y);
            reinterpret_cast<uint4*>(Pp)[0] = u;
            u.x = cvt2(accP[4][0] + bias1[4].x, accP[4][1] + bias1[4].y);
            u.y = cvt2(accP[5][0] + bias1[5].x, accP[5][1] + bias1[5].y);
            u.z = cvt2(accP[6][0] + bias1[6].x, accP[6][1] + bias1[6].y);
            u.w = cvt2(accP[7][0] + bias1[7].x, accP[7][1] + bias1[7].y);
            reinterpret_cast<uint4*>(Pp)[1] = u;
            u.x = cvt2(accQ[0][0], accQ[0][1]);
            u.y = cvt2(accQ[1][0], accQ[1][1]);
            u.z = cvt2(accQ[2][0], accQ[2][1]);
            u.w = cvt2(accQ[3][0], accQ[3][1]);
            reinterpret_cast<uint4*>(Qp)[0] = u;
            u.x = cvt2(accQ[4][0], accQ[4][1]);
            u.y = cvt2(accQ[5][0], accQ[5][1]);
            u.z = cvt2(accQ[6][0], accQ[6][1]);
            u.w = cvt2(accQ[7][0], accQ[7][1]);
            reinterpret_cast<uint4*>(Qp)[1] = u;
        }
        if (r1n < N) {
            uint32_t* Pp = reinterpret_cast<uint32_t*>(g_P + (size_t)r1n * HID) + 8 * tq;
            uint32_t* Qp = reinterpret_cast<uint32_t*>(g_Q + (size_t)r1n * HID) + 8 * tq;
            u.x = cvt2(accP[0][2] + bias1[0].x, accP[0][3] + bias1[0].y);
            u.y = cvt2(accP[1][2] + bias1[1].x, accP[1][3] + bias1[1].y);
            u.z = cvt2(accP[2][2] + bias1[2].x, accP[2][3] + bias1[2].y);
            u.w = cvt2(accP[3][2] + bias1[3].x, accP[3][3] + bias1[3].y);
            reinterpret_cast<uint4*>(Pp)[0] = u;
            u.x = cvt2(accP[4][2] + bias1[4].x, accP[4][3] + bias1[4].y);
            u.y = cvt2(accP[5][2] + bias1[5].x, accP[5][3] + bias1[5].y);
            u.z = cvt2(accP[6][2] + bias1[6].x, accP[6][3] + bias1[6].y);
            u.w = cvt2(accP[7][2] + bias1[7].x, accP[7][3] + bias1[7].y);
            reinterpret_cast<uint4*>(Pp)[1] = u;
            u.x = cvt2(accQ[0][2], accQ[0][3]);
            u.y = cvt2(accQ[1][2], accQ[1][3]);
            u.z = cvt2(accQ[2][2], accQ[2][3]);
            u.w = cvt2(accQ[3][2], accQ[3][3]);
            reinterpret_cast<uint4*>(Qp)[0] = u;
            u.x = cvt2(accQ[4][2], accQ[4][3]);
            u.y = cvt2(accQ[5][2], accQ[5][3]);
            u.z = cvt2(accQ[6][2], accQ[6][3]);
            u.w = cvt2(accQ[7][2], accQ[7][3]);
            reinterpret_cast<uint4*>(Qp)[1] = u;
        }
        __syncwarp();
    }
}

// ---------------------------------------------------------------------------
// Edge kernel: 512 thr (16 warps), 1 CTA/SM. Row layout per staged edge:
// [0,128) P[src] | [128,256) Q[dst] | pad to 272B. 2-stage cp.async pipeline.
// ea + dst loaded direct from global (coalesced rows).
// ---------------------------------------------------------------------------
__global__ void __launch_bounds__(512, 1)
edge_kernel(const int* __restrict__ eidx, const float* __restrict__ ea,
            const float* __restrict__ W1, int E, int nt) {
    extern __shared__ __align__(16) char smraw[];
    __nv_bfloat16* sW1c = reinterpret_cast<__nv_bfloat16*>(smraw);  // 16*88
    char* sP = smraw + 16 * LDW_H * 2;                              // 16w*32*272

    const int tid = threadIdx.x;
    for (int i = tid; i < 16 * HID; i += 512) {
        int k = i >> 6, n = i & 63;
        sW1c[k * LDW_H + n] = __float2bfloat16_rn(W1[(128 + k) * HID + n]);
    }
    __syncthreads();

    const int wid = tid >> 5, lane = tid & 31;
    const int gq = lane >> 2, tq = lane & 3;
    const int el = lane >> 1, part = lane & 1;

    const uint32_t w1cBase = s2u(sW1c) + (((lane & 15) * LDW_H) + 8 * (lane >> 4)) * 2;
    uint32_t w1f[4][4];
#pragma unroll
    for (int nb = 0; nb < 4; nb++)
        ldsm_x4t(w1cBase + (nb * 16) * 2, w1f[nb][0], w1f[nb][1],
                 w1f[nb][2], w1f[nb][3]);

    const int gw = blockIdx.x * 16 + wid;
    const int gs = gridDim.x * 16;
    const int* __restrict__ srcp = eidx;
    const int* __restrict__ dstp = eidx + E;
    const int* __restrict__ idxp = part ? dstp : srcp;

    char* myP = sP + wid * 32 * ROWB;
    const uint32_t myPU = s2u(myP);
    const __nv_bfloat16* gsrc = part ? g_Q : g_P;

    // prologue: gather tile gw into stage 0
    {
        const int e0 = gw * 16 + el;
        if (gw < nt && e0 < E) {
            const int idx = idxp[e0];
            const char* s = reinterpret_cast<const char*>(gsrc + (size_t)idx * HID);
            const uint32_t rb = myPU + (uint32_t)el * ROWB + part * 128;
#pragma unroll
            for (int i = 0; i < 8; i++) cp16(rb + i * 16, s + i * 16);
        }
    }
    asm volatile("cp.async.commit_group;" ::: "memory");
    int idxN = -1;
    {
        const int tn = gw + gs, en = tn * 16 + el;
        if (tn < nt && en < E) idxN = idxp[en];
    }

    int it = 0;
    for (int t = gw; t < nt; t += gs, it++) {
        const int s = it & 1;
        const int r0 = s * 16;
        const int tn = t + gs;

        // issue next stage
        if (tn < nt && idxN >= 0) {
            const char* sg = reinterpret_cast<const char*>(gsrc + (size_t)idxN * HID);
            const uint32_t rb = myPU + (uint32_t)((s ^ 1) * 16 + el) * ROWB + part * 128;
#pragma unroll
            for (int i = 0; i < 8; i++) cp16(rb + i * 16, sg + i * 16);
        }
        asm volatile("cp.async.commit_group;" ::: "memory");
        {
            const int t2 = tn + gs, e2 = t2 * 16 + el;
            idxN = (t2 < nt && e2 < E) ? idxp[e2] : -1;
        }

        // direct loads for current tile (independent of cp.async)
        const int eA = t * 16 + gq, eB = eA + 8;
        const int dA = (eA < E) ? dstp[eA] : -1;
        const int dB = (eB < E) ? dstp[eB] : -1;
        float2 e0 = make_float2(0.f, 0.f), e1 = e0, e2v = e0, e3 = e0;
        if (dA >= 0) {
            const float2* p = reinterpret_cast<const float2*>(ea + (size_t)eA * EDIM);
            e0 = p[tq]; e1 = p[tq + 4];
        }
        if (dB >= 0) {
            const float2* p = reinterpret_cast<const float2*>(ea + (size_t)eB * EDIM);
            e2v = p[tq]; e3 = p[tq + 4];
        }

        asm volatile("cp.async.wait_group 1;" ::: "memory");
        __syncwarp();

        // P/Q epilogue operands: 2x LDS.128 each
        uint32_t pA[8], qA[8], pB[8], qB[8];
        {
            const char* rowA = myP + (r0 + gq) * ROWB;
            const char* rowB = myP + (r0 + gq + 8) * ROWB;
            *reinterpret_cast<uint4*>(&pA[0]) = *reinterpret_cast<const uint4*>(rowA + tq * 32);
            *reinterpret_cast<uint4*>(&pA[4]) = *reinterpret_cast<const uint4*>(rowA + tq * 32 + 16);
            *reinterpret_cast<uint4*>(&qA[0]) = *reinterpret_cast<const uint4*>(rowA + 128 + tq * 32);
            *reinterpret_cast<uint4*>(&qA[4]) = *reinterpret_cast<const uint4*>(rowA + 128 + tq * 32 + 16);
            *reinterpret_cast<uint4*>(&pB[0]) = *reinterpret_cast<const uint4*>(rowB + tq * 32);
            *reinterpret_cast<uint4*>(&pB[4]) = *reinterpret_cast<const uint4*>(rowB + tq * 32 + 16);
            *reinterpret_cast<uint4*>(&qB[0]) = *reinterpret_cast<const uint4*>(rowB + 128 + tq * 32);
            *reinterpret_cast<uint4*>(&qB[4]) = *reinterpret_cast<const uint4*>(rowB + 128 + tq * 32 + 16);
        }

        // A fragment from ea
        const uint32_t a0 = cvt2(e0.x, e0.y);
        const uint32_t a1 = cvt2(e2v.x, e2v.y);
        const uint32_t a2 = cvt2(e1.x, e1.y);
        const uint32_t a3 = cvt2(e3.x, e3.y);

        // MMA: ea(16x16) @ W1c(16x64)
        float acc[8][4];
#pragma unroll
        for (int j = 0; j < 8; j++)
#pragma unroll
            for (int q = 0; q < 4; q++) acc[j][q] = 0.f;
#pragma unroll
        for (int nb = 0; nb < 4; nb++) {
            mma16816(acc[2 * nb],     a0, a1, a2, a3, w1f[nb][0], w1f[nb][1]);
            mma16816(acc[2 * nb + 1], a0, a1, a2, a3, w1f[nb][2], w1f[nb][3]);
        }

        // h = relu(acc + P[src] + Q[dst])  (b1 folded into P)
#pragma unroll
        for (int j = 0; j < 8; j++) {
            float2 pa = bf2f(pA[j]), qa = bf2f(qA[j]);
            float2 pb = bf2f(pB[j]), qb = bf2f(qB[j]);
            acc[j][0] = fmaxf(acc[j][0] + pa.x + qa.x, 0.f);
            acc[j][1] = fmaxf(acc[j][1] + pa.y + qa.y, 0.f);
            acc[j][2] = fmaxf(acc[j][2] + pb.x + qb.x, 0.f);
            acc[j][3] = fmaxf(acc[j][3] + pb.y + qb.y, 0.f);
        }

        // scatter: permuted agg rows are contiguous 64B per lane -> 4 RED.128
        if (dA >= 0) {
            float* b = g_agg + (size_t)dA * HID + tq * 16;
            atomicAdd(reinterpret_cast<float4*>(b + 0),
                      make_float4(acc[0][0], acc[0][1], acc[1][0], acc[1][1]));
            atomicAdd(reinterpret_cast<float4*>(b + 4),
                      make_float4(acc[2][0], acc[2][1], acc[3][0], acc[3][1]));
            atomicAdd(reinterpret_cast<float4*>(b + 8),
                      make_float4(acc[4][0], acc[4][1], acc[5][0], acc[5][1]));
            atomicAdd(reinterpret_cast<float4*>(b + 12),
                      make_float4(acc[6][0], acc[6][1], acc[7][0], acc[7][1]));
            if (tq == 0) atomicAdd(&g_cnt[dA], 1.0f);
        }
        if (dB >= 0) {
            float* b = g_agg + (size_t)dB * HID + tq * 16;
            atomicAdd(reinterpret_cast<float4*>(b + 0),
                      make_float4(acc[0][2], acc[0][3], acc[1][2], acc[1][3]));
            atomicAdd(reinterpret_cast<float4*>(b + 4),
                      make_float4(acc[2][2], acc[2][3], acc[3][2], acc[3][3]));
            atomicAdd(reinterpret_cast<float4*>(b + 8),
                      make_float4(acc[4][2], acc[4][3], acc[5][2], acc[5][3]));
            atomicAdd(reinterpret_cast<float4*>(b + 12),
                      make_float4(acc[6][2], acc[6][3], acc[7][2], acc[7][3]));
            if (tq == 1) atomicAdd(&g_cnt[dB], 1.0f);
        }
        __syncwarp();
    }
}

// ---------------------------------------------------------------------------
// Node kernel: out = x + relu([x, mean_h'] @ Wu2 + bu + f*b2u). agg/Wu2 both
// permuted consistently, so code is unchanged from R10.
// ---------------------------------------------------------------------------
#define FMA16(ACC, AV, BV)                                                    \
  ACC[0][0] = fmaf(AV.x, BV.x, ACC[0][0]);                                    \
  ACC[0][1] = fmaf(AV.x, BV.y, ACC[0][1]);                                    \
  ACC[0][2] = fmaf(AV.x, BV.z, ACC[0][2]);                                    \
  ACC[0][3] = fmaf(AV.x, BV.w, ACC[0][3]);                                    \
  ACC[1][0] = fmaf(AV.y, BV.x, ACC[1][0]);                                    \
  ACC[1][1] = fmaf(AV.y, BV.y, ACC[1][1]);                                    \
  ACC[1][2] = fmaf(AV.y, BV.z, ACC[1][2]);                                    \
  ACC[1][3] = fmaf(AV.y, BV.w, ACC[1][3]);                                    \
  ACC[2][0] = fmaf(AV.z, BV.x, ACC[2][0]);                                    \
  ACC[2][1] = fmaf(AV.z, BV.y, ACC[2][1]);                                    \
  ACC[2][2] = fmaf(AV.z, BV.z, ACC[2][2]);                                    \
  ACC[2][3] = fmaf(AV.z, BV.w, ACC[2][3]);                                    \
  ACC[3][0] = fmaf(AV.w, BV.x, ACC[3][0]);                                    \
  ACC[3][1] = fmaf(AV.w, BV.y, ACC[3][1]);                                    \
  ACC[3][2] = fmaf(AV.w, BV.z, ACC[3][2]);                                    \
  ACC[3][3] = fmaf(AV.w, BV.w, ACC[3][3]);

__global__ void __launch_bounds__(256, 3)
node_kernel(const float* __restrict__ x, const float* __restrict__ bu,
            float* __restrict__ out, int N, int ntiles) {
    extern __shared__ float smn[];
    float* sWu  = smn;
    float* sIn  = sWu + 2 * ND * HID;
    float* sBu  = sIn + 2 * ND * TILE_N;
    float* sB2u = sBu + HID;
    float* sF   = sB2u + HID;

    const int tid = threadIdx.x;
    for (int i = tid; i < 2 * ND * HID; i += 256) sWu[i] = g_Wu2[i];
    if (tid < HID) { sBu[tid] = bu[tid]; sB2u[tid] = g_b2u[tid]; }
    __syncthreads();

    const int tx = tid & 15;
    const int ty = tid >> 4;
    const int q  = tid & 3;
    const int ng = tid >> 2;

    for (int tile = blockIdx.x; tile < ntiles; tile += gridDim.x) {
        const int n0 = tile * TILE_N;
        {
            const int n = n0 + ng;
            if (n < N) {
                const float cnt = g_cnt[n];
                const float inv = 1.0f / (cnt + 1e-6f);
                if (q == 0) sF[ng] = cnt * inv;
                const float4* xr = reinterpret_cast<const float4*>(x + (size_t)n * ND);
                const float4* ar = reinterpret_cast<const float4*>(g_agg + (size_t)n * HID);
#pragma unroll
                for (int i = 0; i < 4; i++) {
                    const int f4 = q + 4 * i;
                    const int k  = f4 * 4;
                    float4 v = xr[f4];
                    sIn[(k + 0) * TILE_N + ng] = v.x;
                    sIn[(k + 1) * TILE_N + ng] = v.y;
                    sIn[(k + 2) * TILE_N + ng] = v.z;
                    sIn[(k + 3) * TILE_N + ng] = v.w;
                    float4 w = ar[f4];
                    sIn[(ND + k + 0) * TILE_N + ng] = w.x * inv;
                    sIn[(ND + k + 1) * TILE_N + ng] = w.y * inv;
                    sIn[(ND + k + 2) * TILE_N + ng] = w.z * inv;
                    sIn[(ND + k + 3) * TILE_N + ng] = w.w * inv;
                }
            }
        }
        __syncthreads();

        float acc[4][4];
#pragma unroll
        for (int a = 0; a < 4; a++)
#pragma unroll
            for (int b = 0; b < 4; b++) acc[a][b] = 0.f;

#pragma unroll 8
        for (int k = 0; k < 2 * ND; k++) {
            float4 av = *reinterpret_cast<const float4*>(&sIn[k * TILE_N + tx * 4]);
            float4 bv = *reinterpret_cast<const float4*>(&sWu[k * HID + ty * 4]);
            FMA16(acc, av, bv)
        }

#pragma unroll
        for (int ei = 0; ei < 4; ei++) {
            const int n = n0 + tx * 4 + ei;
            if (n < N) {
                const float f = sF[tx * 4 + ei];
                float4 o;
                float r;
                r = acc[ei][0] + sBu[ty * 4 + 0] + f * sB2u[ty * 4 + 0];
                o.x = sIn[(ty * 4 + 0) * TILE_N + tx * 4 + ei] + (r > 0.f ? r : 0.f);
                r = acc[ei][1] + sBu[ty * 4 + 1] + f * sB2u[ty * 4 + 1];
                o.y = sIn[(ty * 4 + 1) * TILE_N + tx * 4 + ei] + (r > 0.f ? r : 0.f);
                r = acc[ei][2] + sBu[ty * 4 + 2] + f * sB2u[ty * 4 + 2];
                o.z = sIn[(ty * 4 + 2) * TILE_N + tx * 4 + ei] + (r > 0.f ? r : 0.f);
                r = acc[ei][3] + sBu[ty * 4 + 3] + f * sB2u[ty * 4 + 3];
                o.w = sIn[(ty * 4 + 3) * TILE_N + tx * 4 + ei] + (r > 0.f ? r : 0.f);
                *reinterpret_cast<float4*>(out + (size_t)n * HID + ty * 4) = o;
            }
        }
        __syncthreads();
    }
}

// ---------------------------------------------------------------------------
extern "C" void kernel_launch(void* const* d_in, const int* in_sizes, int n_in,
                              void* d_out, int out_size) {
    const float* x   = (const float*)d_in[0];
    const int*   ei  = (const int*)d_in[1];
    const float* ea  = (const float*)d_in[2];
    const float* W1  = (const float*)d_in[3];
    const float* b1  = (const float*)d_in[4];
    const float* W2  = (const float*)d_in[5];
    const float* b2  = (const float*)d_in[6];
    const float* Wu  = (const float*)d_in[7];
    const float* bu  = (const float*)d_in[8];
    float* out = (float*)d_out;

    const int N = in_sizes[0] / ND;     // 100000
    const int E = in_sizes[2] / EDIM;   // 1600000

    const int smem_pq   = (2 * 64 * LDW_H + 8 * 16 * LDX_H) * 2;
    const int smem_edge = 16 * LDW_H * 2 + 16 * 32 * ROWB;     // 142080
    const int smem_node = (2 * ND * HID + 2 * ND * TILE_N + 3 * HID) * 4;

    cudaFuncSetAttribute(pq_kernel, cudaFuncAttributeMaxDynamicSharedMemorySize,
                         smem_pq);
    cudaFuncSetAttribute(edge_kernel, cudaFuncAttributeMaxDynamicSharedMemorySize,
                         smem_edge);
    cudaFuncSetAttribute(node_kernel, cudaFuncAttributeMaxDynamicSharedMemorySize,
                         smem_node);

    const int npq = (N + 15) / 16;
    const int nst = (E + 15) / 16;
    const int ntiles = (N + TILE_N - 1) / TILE_N;

    zero_kernel<<<2048, 256>>>(N);
    w2u_kernel<<<(2 * ND * HID + HID + 255) / 256, 256>>>(W2, Wu, b2);
    pq_kernel<<<(npq + 7) / 8, 256, smem_pq>>>(x, W1, b1, N, npq);
    edge_kernel<<<148, 512, smem_edge>>>(ei, ea, W1, E, nst);
    node_kernel<<<456, 256, smem_node>>>(x, bu, out, N, ntiles);
}

// round 13
// speedup vs baseline: 1.6631x; 1.2017x over previous
#include <cuda_runtime.h>
#include <cuda_bf16.h>
#include <cstdint>

// EdgeConv: message MLP over edges + mean-aggregate + update MLP + residual.
// R13: R12 + edge kernel loads P/Q DIRECTLY from global as LDG.128 pairs
// (permuted fragment layout makes lane operands 32B-contiguous). No cp.async,
// no SMEM P/Q buffer, no LDS, no syncwarp in the loop. W2 folded into Wu.

#define ND      64
#define EDIM    16
#define HID     64
#define TILE_N  64
#define MAXN    100000

#define LDW_H   88    // bf16 weight row stride (176B)
#define LDX_H   72    // pq x-tile row stride (144B)

__device__ float         g_agg[(size_t)MAXN * HID];   // permuted h-sums
__device__ float         g_cnt[MAXN];
__device__ __nv_bfloat16 g_P[(size_t)MAXN * HID];     // permuted x@W1a + b1
__device__ __nv_bfloat16 g_Q[(size_t)MAXN * HID];     // permuted x@W1b
__device__ float         g_Wu2[2 * ND * HID];         // [Wu_top; perm(W2@Wu_bot)]
__device__ float         g_b2u[HID];

static __device__ __forceinline__ uint32_t s2u(const void* p) {
    return (uint32_t)__cvta_generic_to_shared(p);
}
static __device__ __forceinline__ void ldsm_x4(uint32_t addr, uint32_t& r0,
                                               uint32_t& r1, uint32_t& r2,
                                               uint32_t& r3) {
    asm volatile("ldmatrix.sync.aligned.m8n8.x4.shared.b16 {%0,%1,%2,%3}, [%4];"
                 : "=r"(r0), "=r"(r1), "=r"(r2), "=r"(r3) : "r"(addr));
}
static __device__ __forceinline__ void ldsm_x4t(uint32_t addr, uint32_t& r0,
                                                uint32_t& r1, uint32_t& r2,
                                                uint32_t& r3) {
    asm volatile("ldmatrix.sync.aligned.m8n8.x4.trans.shared.b16 {%0,%1,%2,%3}, [%4];"
                 : "=r"(r0), "=r"(r1), "=r"(r2), "=r"(r3) : "r"(addr));
}
static __device__ __forceinline__ void mma16816(float* c, uint32_t a0, uint32_t a1,
                                                uint32_t a2, uint32_t a3,
                                                uint32_t b0, uint32_t b1) {
    asm volatile(
        "mma.sync.aligned.m16n8k16.row.col.f32.bf16.bf16.f32 "
        "{%0,%1,%2,%3}, {%4,%5,%6,%7}, {%8,%9}, {%0,%1,%2,%3};"
        : "+f"(c[0]), "+f"(c[1]), "+f"(c[2]), "+f"(c[3])
        : "r"(a0), "r"(a1), "r"(a2), "r"(a3), "r"(b0), "r"(b1));
}
static __device__ __forceinline__ uint32_t cvt2(float lo, float hi) {
    __nv_bfloat162 p = __floats2bfloat162_rn(lo, hi);
    return *reinterpret_cast<uint32_t*>(&p);
}
static __device__ __forceinline__ float2 bf2f(uint32_t u) {
    return __bfloat1622float2(*reinterpret_cast<__nv_bfloat162*>(&u));
}

// ---------------------------------------------------------------------------
__global__ void zero_kernel(int N) {
    long long i = (long long)blockIdx.x * blockDim.x + threadIdx.x;
    long long stride = (long long)gridDim.x * blockDim.x;
    float4* a4 = reinterpret_cast<float4*>(g_agg);
    long long n4 = (long long)N * (HID / 4);
    float4 z = make_float4(0.f, 0.f, 0.f, 0.f);
    for (long long j = i; j < n4; j += stride) a4[j] = z;
    for (long long j = i; j < N; j += stride) g_cnt[j] = 0.f;
}

// ---------------------------------------------------------------------------
// w2u: top = Wu rows [0,64); bottom permuted row r <- m = 8j+2t+b where
// r = 16t+2j+b. b2u = b2 @ Wu_bot.
// ---------------------------------------------------------------------------
__global__ void w2u_kernel(const float* __restrict__ W2,
                           const float* __restrict__ Wu,
                           const float* __restrict__ b2) {
    int i = blockIdx.x * blockDim.x + threadIdx.x;
    if (i < ND * HID) {
        g_Wu2[i] = Wu[i];
    } else if (i < 2 * ND * HID) {
        int r = (i - ND * HID) >> 6, n = i & 63;
        int tt = r >> 4, jj = (r & 15) >> 1, bb = r & 1;
        int m = 8 * jj + 2 * tt + bb;
        float s = 0.f;
        for (int k = 0; k < HID; k++)
            s += W2[m * HID + k] * Wu[(ND + k) * HID + n];
        g_Wu2[i] = s;
    } else if (i < 2 * ND * HID + HID) {
        int n = i - 2 * ND * HID;
        float s = 0.f;
        for (int k = 0; k < HID; k++)
            s += b2[k] * Wu[(ND + k) * HID + n];
        g_b2u[n] = s;
    }
}

// ---------------------------------------------------------------------------
// pq_kernel: P = x@W1[0:64] + b1, Q = x@W1[64:128]; permuted bf16 outputs.
// ---------------------------------------------------------------------------
__global__ void __launch_bounds__(256)
pq_kernel(const float* __restrict__ x, const float* __restrict__ W1,
          const float* __restrict__ b1, int N, int ntiles) {
    extern __shared__ __align__(16) char smq[];
    __nv_bfloat16* sWa = reinterpret_cast<__nv_bfloat16*>(smq);
    __nv_bfloat16* sWb = sWa + 64 * LDW_H;
    __nv_bfloat16* sX  = sWb + 64 * LDW_H;

    const int tid = threadIdx.x;
    for (int i = tid; i < 64 * 64; i += 256) {
        int k = i >> 6, n = i & 63;
        sWa[k * LDW_H + n] = __float2bfloat16_rn(W1[k * HID + n]);
        sWb[k * LDW_H + n] = __float2bfloat16_rn(W1[(64 + k) * HID + n]);
    }
    __syncthreads();

    const int wid = tid >> 5, lane = tid & 31;
    const int gq = lane >> 2, tq = lane & 3;
    const int el = lane >> 1, part = lane & 1;

    float2 bias1[8];
#pragma unroll
    for (int j = 0; j < 8; j++) {
        bias1[j].x = b1[8 * j + 2 * tq];
        bias1[j].y = b1[8 * j + 2 * tq + 1];
    }

    __nv_bfloat16* myX = sX + wid * 16 * LDX_H;
    const uint32_t xBase = s2u(myX) + (((lane & 15) * LDX_H) + 8 * (lane >> 4)) * 2;
    const uint32_t waBase = s2u(sWa) + (((lane & 15) * LDW_H) + 8 * (lane >> 4)) * 2;
    const uint32_t wbBase = s2u(sWb) + (((lane & 15) * LDW_H) + 8 * (lane >> 4)) * 2;

    for (int t = blockIdx.x * 8 + wid; t < ntiles; t += gridDim.x * 8) {
        const int n0 = t * 16;
        {
            const int n = n0 + el;
            uint4* dst = reinterpret_cast<uint4*>(myX + el * LDX_H + part * 32);
            if (n < N) {
                const float4* xr = reinterpret_cast<const float4*>(
                    x + (size_t)n * ND) + part * 8;
#pragma unroll
                for (int i = 0; i < 4; i++) {
                    float4 a = xr[2 * i], b = xr[2 * i + 1];
                    uint4 u;
                    u.x = cvt2(a.x, a.y); u.y = cvt2(a.z, a.w);
                    u.z = cvt2(b.x, b.y); u.w = cvt2(b.z, b.w);
                    dst[i] = u;
                }
            } else {
                uint4 z = make_uint4(0, 0, 0, 0);
#pragma unroll
                for (int i = 0; i < 4; i++) dst[i] = z;
            }
        }
        __syncwarp();

        float accP[8][4], accQ[8][4];
#pragma unroll
        for (int j = 0; j < 8; j++)
#pragma unroll
            for (int q = 0; q < 4; q++) { accP[j][q] = 0.f; accQ[j][q] = 0.f; }

#pragma unroll
        for (int k = 0; k < 4; k++) {
            uint32_t a0, a1, a2, a3;
            ldsm_x4(xBase + k * 32, a0, a1, a2, a3);
#pragma unroll
            for (int nb = 0; nb < 4; nb++) {
                uint32_t p0, p1, p2, p3;
                ldsm_x4t(waBase + (k * 16 * LDW_H + nb * 16) * 2, p0, p1, p2, p3);
                mma16816(accP[2 * nb],     a0, a1, a2, a3, p0, p1);
                mma16816(accP[2 * nb + 1], a0, a1, a2, a3, p2, p3);
                ldsm_x4t(wbBase + (k * 16 * LDW_H + nb * 16) * 2, p0, p1, p2, p3);
                mma16816(accQ[2 * nb],     a0, a1, a2, a3, p0, p1);
                mma16816(accQ[2 * nb + 1], a0, a1, a2, a3, p2, p3);
            }
        }

        const int r0n = n0 + gq, r1n = n0 + gq + 8;
        uint4 u;
        if (r0n < N) {
            uint32_t* Pp = reinterpret_cast<uint32_t*>(g_P + (size_t)r0n * HID) + 8 * tq;
            uint32_t* Qp = reinterpret_cast<uint32_t*>(g_Q + (size_t)r0n * HID) + 8 * tq;
            u.x = cvt2(accP[0][0] + bias1[0].x, accP[0][1] + bias1[0].y);
            u.y = cvt2(accP[1][0] + bias1[1].x, accP[1][1] + bias1[1].y);
            u.z = cvt2(accP[2][0] + bias1[2].x, accP[2][1] + bias1[2].y);
            u.w = cvt2(accP[3][0] + bias1[3].x, accP[3][1] + bias1[3].y);
            reinterpret_cast<uint4*>(Pp)[0] = u;
            u.x = cvt2(accP[4][0] + bias1[4].x, accP[4][1] + bias1[4].y);
            u.y = cvt2(accP[5][0] + bias1[5].x, accP[5][1] + bias1[5].y);
            u.z = cvt2(accP[6][0] + bias1[6].x, accP[6][1] + bias1[6].y);
            u.w = cvt2(accP[7][0] + bias1[7].x, accP[7][1] + bias1[7].y);
            reinterpret_cast<uint4*>(Pp)[1] = u;
            u.x = cvt2(accQ[0][0], accQ[0][1]);
            u.y = cvt2(accQ[1][0], accQ[1][1]);
            u.z = cvt2(accQ[2][0], accQ[2][1]);
            u.w = cvt2(accQ[3][0], accQ[3][1]);
            reinterpret_cast<uint4*>(Qp)[0] = u;
            u.x = cvt2(accQ[4][0], accQ[4][1]);
            u.y = cvt2(accQ[5][0], accQ[5][1]);
            u.z = cvt2(accQ[6][0], accQ[6][1]);
            u.w = cvt2(accQ[7][0], accQ[7][1]);
            reinterpret_cast<uint4*>(Qp)[1] = u;
        }
        if (r1n < N) {
            uint32_t* Pp = reinterpret_cast<uint32_t*>(g_P + (size_t)r1n * HID) + 8 * tq;
            uint32_t* Qp = reinterpret_cast<uint32_t*>(g_Q + (size_t)r1n * HID) + 8 * tq;
            u.x = cvt2(accP[0][2] + bias1[0].x, accP[0][3] + bias1[0].y);
            u.y = cvt2(accP[1][2] + bias1[1].x, accP[1][3] + bias1[1].y);
            u.z = cvt2(accP[2][2] + bias1[2].x, accP[2][3] + bias1[2].y);
            u.w = cvt2(accP[3][2] + bias1[3].x, accP[3][3] + bias1[3].y);
            reinterpret_cast<uint4*>(Pp)[0] = u;
            u.x = cvt2(accP[4][2] + bias1[4].x, accP[4][3] + bias1[4].y);
            u.y = cvt2(accP[5][2] + bias1[5].x, accP[5][3] + bias1[5].y);
            u.z = cvt2(accP[6][2] + bias1[6].x, accP[6][3] + bias1[6].y);
            u.w = cvt2(accP[7][2] + bias1[7].x, accP[7][3] + bias1[7].y);
            reinterpret_cast<uint4*>(Pp)[1] = u;
            u.x = cvt2(accQ[0][2], accQ[0][3]);
            u.y = cvt2(accQ[1][2], accQ[1][3]);
            u.z = cvt2(accQ[2][2], accQ[2][3]);
            u.w = cvt2(accQ[3][2], accQ[3][3]);
            reinterpret_cast<uint4*>(Qp)[0] = u;
            u.x = cvt2(accQ[4][2], accQ[4][3]);
            u.y = cvt2(accQ[5][2], accQ[5][3]);
            u.z = cvt2(accQ[6][2], accQ[6][3]);
            u.w = cvt2(accQ[7][2], accQ[7][3]);
            reinterpret_cast<uint4*>(Qp)[1] = u;
        }
        __syncwarp();
    }
}

// ---------------------------------------------------------------------------
// Edge kernel: 512 thr (16 warps), 1 CTA/SM. No SMEM except W1c; per tile of
// 16 edges, lane loads its permuted P/Q operands as 8x LDG.128, ea as 4x
// LDG.64, MMA, epilogue add+relu, RED.128 scatter. Index prefetch 1 tile ahead.
// ---------------------------------------------------------------------------
__global__ void __launch_bounds__(512, 1)
edge_kernel(const int* __restrict__ eidx, const float* __restrict__ ea,
            const float* __restrict__ W1, int E, int nt) {
    __shared__ __align__(16) __nv_bfloat16 sW1c[16 * LDW_H];
    const int tid = threadIdx.x;
    for (int i = tid; i < 16 * HID; i += 512) {
        int k = i >> 6, n = i & 63;
        sW1c[k * LDW_H + n] = __float2bfloat16_rn(W1[(128 + k) * HID + n]);
    }
    __syncthreads();

    const int wid = tid >> 5, lane = tid & 31;
    const int gq = lane >> 2, tq = lane & 3;

    const uint32_t w1cBase = s2u(sW1c) + (((lane & 15) * LDW_H) + 8 * (lane >> 4)) * 2;
    uint32_t w1f[4][4];
#pragma unroll
    for (int nb = 0; nb < 4; nb++)
        ldsm_x4t(w1cBase + (nb * 16) * 2, w1f[nb][0], w1f[nb][1],
                 w1f[nb][2], w1f[nb][3]);

    const int gw = blockIdx.x * 16 + wid;
    const int gs = gridDim.x * 16;
    const int* __restrict__ srcp = eidx;
    const int* __restrict__ dstp = eidx + E;

    // prefetch indices for first tile (rows gq and gq+8)
    int sA = 0, sB = 0, dA = -1, dB = -1;
    if (gw < nt) {
        const int eA = gw * 16 + gq, eB = eA + 8;
        if (eA < E) { sA = srcp[eA]; dA = dstp[eA]; }
        if (eB < E) { sB = srcp[eB]; dB = dstp[eB]; }
    }

    for (int t = gw; t < nt; t += gs) {
        // ---- issue P/Q direct loads (permuted: 32B contiguous per lane) ----
        const uint4* PsA = reinterpret_cast<const uint4*>(g_P + (size_t)sA * HID) + 2 * tq;
        const uint4* QdA = reinterpret_cast<const uint4*>(g_Q + (size_t)((dA >= 0) ? dA : 0) * HID) + 2 * tq;
        const uint4* PsB = reinterpret_cast<const uint4*>(g_P + (size_t)sB * HID) + 2 * tq;
        const uint4* QdB = reinterpret_cast<const uint4*>(g_Q + (size_t)((dB >= 0) ? dB : 0) * HID) + 2 * tq;
        uint32_t pA[8], qA[8], pB[8], qB[8];
        *reinterpret_cast<uint4*>(&pA[0]) = PsA[0];
        *reinterpret_cast<uint4*>(&pA[4]) = PsA[1];
        *reinterpret_cast<uint4*>(&qA[0]) = QdA[0];
        *reinterpret_cast<uint4*>(&qA[4]) = QdA[1];
        *reinterpret_cast<uint4*>(&pB[0]) = PsB[0];
        *reinterpret_cast<uint4*>(&pB[4]) = PsB[1];
        *reinterpret_cast<uint4*>(&qB[0]) = QdB[0];
        *reinterpret_cast<uint4*>(&qB[4]) = QdB[1];

        // ---- ea loads (coalesced rows) ----
        const int eA = t * 16 + gq, eB = eA + 8;
        float2 e0 = make_float2(0.f, 0.f), e1 = e0, e2v = e0, e3 = e0;
        if (dA >= 0) {
            const float2* p = reinterpret_cast<const float2*>(ea + (size_t)eA * EDIM);
            e0 = p[tq]; e1 = p[tq + 4];
        }
        if (dB >= 0) {
            const float2* p = reinterpret_cast<const float2*>(ea + (size_t)eB * EDIM);
            e2v = p[tq]; e3 = p[tq + 4];
        }

        // ---- prefetch indices for next tile (overlaps compute) ----
        const int curdA = dA, curdB = dB;
        {
            const int tn = t + gs;
            int nsA = 0, nsB = 0, ndA = -1, ndB = -1;
            if (tn < nt) {
                const int neA = tn * 16 + gq, neB = neA + 8;
                if (neA < E) { nsA = srcp[neA]; ndA = dstp[neA]; }
                if (neB < E) { nsB = srcp[neB]; ndB = dstp[neB]; }
            }
            sA = nsA; sB = nsB; dA = ndA; dB = ndB;
        }

        // ---- A fragment from ea ----
        const uint32_t a0 = cvt2(e0.x, e0.y);
        const uint32_t a1 = cvt2(e2v.x, e2v.y);
        const uint32_t a2 = cvt2(e1.x, e1.y);
        const uint32_t a3 = cvt2(e3.x, e3.y);

        // ---- MMA: ea(16x16) @ W1c(16x64) ----
        float acc[8][4];
#pragma unroll
        for (int j = 0; j < 8; j++)
#pragma unroll
            for (int q = 0; q < 4; q++) acc[j][q] = 0.f;
#pragma unroll
        for (int nb = 0; nb < 4; nb++) {
            mma16816(acc[2 * nb],     a0, a1, a2, a3, w1f[nb][0], w1f[nb][1]);
            mma16816(acc[2 * nb + 1], a0, a1, a2, a3, w1f[nb][2], w1f[nb][3]);
        }

        // ---- h = relu(acc + P[src] + Q[dst]) (b1 folded into P) ----
#pragma unroll
        for (int j = 0; j < 8; j++) {
            float2 pa = bf2f(pA[j]), qa = bf2f(qA[j]);
            float2 pb = bf2f(pB[j]), qb = bf2f(qB[j]);
            acc[j][0] = fmaxf(acc[j][0] + pa.x + qa.x, 0.f);
            acc[j][1] = fmaxf(acc[j][1] + pa.y + qa.y, 0.f);
            acc[j][2] = fmaxf(acc[j][2] + pb.x + qb.x, 0.f);
            acc[j][3] = fmaxf(acc[j][3] + pb.y + qb.y, 0.f);
        }

        // ---- scatter: contiguous 64B per lane in permuted agg ----
        if (curdA >= 0) {
            float* b = g_agg + (size_t)curdA * HID + tq * 16;
            atomicAdd(reinterpret_cast<float4*>(b + 0),
                      make_float4(acc[0][0], acc[0][1], acc[1][0], acc[1][1]));
            atomicAdd(reinterpret_cast<float4*>(b + 4),
                      make_float4(acc[2][0], acc[2][1], acc[3][0], acc[3][1]));
            atomicAdd(reinterpret_cast<float4*>(b + 8),
                      make_float4(acc[4][0], acc[4][1], acc[5][0], acc[5][1]));
            atomicAdd(reinterpret_cast<float4*>(b + 12),
                      make_float4(acc[6][0], acc[6][1], acc[7][0], acc[7][1]));
            if (tq == 0) atomicAdd(&g_cnt[curdA], 1.0f);
        }
        if (curdB >= 0) {
            float* b = g_agg + (size_t)curdB * HID + tq * 16;
            atomicAdd(reinterpret_cast<float4*>(b + 0),
                      make_float4(acc[0][2], acc[0][3], acc[1][2], acc[1][3]));
            atomicAdd(reinterpret_cast<float4*>(b + 4),
                      make_float4(acc[2][2], acc[2][3], acc[3][2], acc[3][3]));
            atomicAdd(reinterpret_cast<float4*>(b + 8),
                      make_float4(acc[4][2], acc[4][3], acc[5][2], acc[5][3]));
            atomicAdd(reinterpret_cast<float4*>(b + 12),
                      make_float4(acc[6][2], acc[6][3], acc[7][2], acc[7][3]));
            if (tq == 1) atomicAdd(&g_cnt[curdB], 1.0f);
        }
    }
}

// ---------------------------------------------------------------------------
// Node kernel: out = x + relu([x, mean_h'] @ Wu2 + bu + f*b2u).
// ---------------------------------------------------------------------------
#define FMA16(ACC, AV, BV)                                                    \
  ACC[0][0] = fmaf(AV.x, BV.x, ACC[0][0]);                                    \
  ACC[0][1] = fmaf(AV.x, BV.y, ACC[0][1]);                                    \
  ACC[0][2] = fmaf(AV.x, BV.z, ACC[0][2]);                                    \
  ACC[0][3] = fmaf(AV.x, BV.w, ACC[0][3]);                                    \
  ACC[1][0] = fmaf(AV.y, BV.x, ACC[1][0]);                                    \
  ACC[1][1] = fmaf(AV.y, BV.y, ACC[1][1]);                                    \
  ACC[1][2] = fmaf(AV.y, BV.z, ACC[1][2]);                                    \
  ACC[1][3] = fmaf(AV.y, BV.w, ACC[1][3]);                                    \
  ACC[2][0] = fmaf(AV.z, BV.x, ACC[2][0]);                                    \
  ACC[2][1] = fmaf(AV.z, BV.y, ACC[2][1]);                                    \
  ACC[2][2] = fmaf(AV.z, BV.z, ACC[2][2]);                                    \
  ACC[2][3] = fmaf(AV.z, BV.w, ACC[2][3]);                                    \
  ACC[3][0] = fmaf(AV.w, BV.x, ACC[3][0]);                                    \
  ACC[3][1] = fmaf(AV.w, BV.y, ACC[3][1]);                                    \
  ACC[3][2] = fmaf(AV.w, BV.z, ACC[3][2]);                                    \
  ACC[3][3] = fmaf(AV.w, BV.w, ACC[3][3]);

__global__ void __launch_bounds__(256, 3)
node_kernel(const float* __restrict__ x, const float* __restrict__ bu,
            float* __restrict__ out, int N, int ntiles) {
    extern __shared__ float smn[];
    float* sWu  = smn;
    float* sIn  = sWu + 2 * ND * HID;
    float* sBu  = sIn + 2 * ND * TILE_N;
    float* sB2u = sBu + HID;
    float* sF   = sB2u + HID;

    const int tid = threadIdx.x;
    for (int i = tid; i < 2 * ND * HID; i += 256) sWu[i] = g_Wu2[i];
    if (tid < HID) { sBu[tid] = bu[tid]; sB2u[tid] = g_b2u[tid]; }
    __syncthreads();

    const int tx = tid & 15;
    const int ty = tid >> 4;
    const int q  = tid & 3;
    const int ng = tid >> 2;

    for (int tile = blockIdx.x; tile < ntiles; tile += gridDim.x) {
        const int n0 = tile * TILE_N;
        {
            const int n = n0 + ng;
            if (n < N) {
                const float cnt = g_cnt[n];
                const float inv = 1.0f / (cnt + 1e-6f);
                if (q == 0) sF[ng] = cnt * inv;
                const float4* xr = reinterpret_cast<const float4*>(x + (size_t)n * ND);
                const float4* ar = reinterpret_cast<const float4*>(g_agg + (size_t)n * HID);
#pragma unroll
                for (int i = 0; i < 4; i++) {
                    const int f4 = q + 4 * i;
                    const int k  = f4 * 4;
                    float4 v = xr[f4];
                    sIn[(k + 0) * TILE_N + ng] = v.x;
                    sIn[(k + 1) * TILE_N + ng] = v.y;
                    sIn[(k + 2) * TILE_N + ng] = v.z;
                    sIn[(k + 3) * TILE_N + ng] = v.w;
                    float4 w = ar[f4];
                    sIn[(ND + k + 0) * TILE_N + ng] = w.x * inv;
                    sIn[(ND + k + 1) * TILE_N + ng] = w.y * inv;
                    sIn[(ND + k + 2) * TILE_N + ng] = w.z * inv;
                    sIn[(ND + k + 3) * TILE_N + ng] = w.w * inv;
                }
            }
        }
        __syncthreads();

        float acc[4][4];
#pragma unroll
        for (int a = 0; a < 4; a++)
#pragma unroll
            for (int b = 0; b < 4; b++) acc[a][b] = 0.f;

#pragma unroll 8
        for (int k = 0; k < 2 * ND; k++) {
            float4 av = *reinterpret_cast<const float4*>(&sIn[k * TILE_N + tx * 4]);
            float4 bv = *reinterpret_cast<const float4*>(&sWu[k * HID + ty * 4]);
            FMA16(acc, av, bv)
        }

#pragma unroll
        for (int ei = 0; ei < 4; ei++) {
            const int n = n0 + tx * 4 + ei;
            if (n < N) {
                const float f = sF[tx * 4 + ei];
                float4 o;
                float r;
                r = acc[ei][0] + sBu[ty * 4 + 0] + f * sB2u[ty * 4 + 0];
                o.x = sIn[(ty * 4 + 0) * TILE_N + tx * 4 + ei] + (r > 0.f ? r : 0.f);
                r = acc[ei][1] + sBu[ty * 4 + 1] + f * sB2u[ty * 4 + 1];
                o.y = sIn[(ty * 4 + 1) * TILE_N + tx * 4 + ei] + (r > 0.f ? r : 0.f);
                r = acc[ei][2] + sBu[ty * 4 + 2] + f * sB2u[ty * 4 + 2];
                o.z = sIn[(ty * 4 + 2) * TILE_N + tx * 4 + ei] + (r > 0.f ? r : 0.f);
                r = acc[ei][3] + sBu[ty * 4 + 3] + f * sB2u[ty * 4 + 3];
                o.w = sIn[(ty * 4 + 3) * TILE_N + tx * 4 + ei] + (r > 0.f ? r : 0.f);
                *reinterpret_cast<float4*>(out + (size_t)n * HID + ty * 4) = o;
            }
        }
        __syncthreads();
    }
}

// ---------------------------------------------------------------------------
extern "C" void kernel_launch(void* const* d_in, const int* in_sizes, int n_in,
                              void* d_out, int out_size) {
    const float* x   = (const float*)d_in[0];
    const int*   ei  = (const int*)d_in[1];
    const float* ea  = (const float*)d_in[2];
    const float* W1  = (const float*)d_in[3];
    const float* b1  = (const float*)d_in[4];
    const float* W2  = (const float*)d_in[5];
    const float* b2  = (const float*)d_in[6];
    const float* Wu  = (const float*)d_in[7];
    const float* bu  = (const float*)d_in[8];
    float* out = (float*)d_out;

    const int N = in_sizes[0] / ND;     // 100000
    const int E = in_sizes[2] / EDIM;   // 1600000

    const int smem_pq   = (2 * 64 * LDW_H + 8 * 16 * LDX_H) * 2;
    const int smem_node = (2 * ND * HID + 2 * ND * TILE_N + 3 * HID) * 4;

    cudaFuncSetAttribute(pq_kernel, cudaFuncAttributeMaxDynamicSharedMemorySize,
                         smem_pq);
    cudaFuncSetAttribute(node_kernel, cudaFuncAttributeMaxDynamicSharedMemorySize,
                         smem_node);

    const int npq = (N + 15) / 16;
    const int nst = (E + 15) / 16;
    const int ntiles = (N + TILE_N - 1) / TILE_N;

    zero_kernel<<<2048, 256>>>(N);
    w2u_kernel<<<(2 * ND * HID + HID + 255) / 256, 256>>>(W2, Wu, b2);
    pq_kernel<<<(npq + 7) / 8, 256, smem_pq>>>(x, W1, b1, N, npq);
    edge_kernel<<<148, 512>>>(ei, ea, W1, E, nst);
    node_kernel<<<456, 256, smem_node>>>(x, bu, out, N, ntiles);
}